// round 8
// baseline (speedup 1.0000x reference)
#include <cuda_runtime.h>

#define Nn 100000
#define Ee 600000
#define Dd 128
#define Gg 256
#define EPSV 1e-5f

typedef unsigned long long ull;

// ---------------- scratch (device globals; no allocation allowed) ----------------
__device__ __align__(16) float d_h[Nn * Dd];     // normed features (GEMM input + gather source)
__device__ __align__(16) float d_agg[Nn * Dd];   // segment-max result
__device__ __align__(16) float d_y[Nn * Dd];     // relu(x + sage) pre-norm2
__device__ __align__(16) float d_s1[Gg * Dd], d_q1[Gg * Dd];
__device__ __align__(16) float d_s2[Gg * Dd], d_q2[Gg * Dd];
__device__ __align__(16) float d_A1[Gg * Dd], d_C1[Gg * Dd];
__device__ __align__(16) float d_A2[Gg * Dd], d_C2[Gg * Dd];
__device__ float d_cnt[Gg];
__device__ int d_deg[Nn], d_start[Nn], d_cur[Nn], d_srcs[Ee];
__device__ int d_bsum[128];

// ---------------- helpers ----------------
__device__ __forceinline__ ull pack2(float v) {
    ull u = (ull)__float_as_uint(v);
    return u | (u << 32);
}
#define FMA2(d, a, b) asm("fma.rn.f32x2 %0, %1, %2, %0;" : "+l"(d) : "l"(a), "l"(b))

// ---------------- zero scratch ----------------
__global__ void zeroKernel() {
    int i = blockIdx.x * blockDim.x + threadIdx.x;
    int stride = gridDim.x * blockDim.x;
    for (int j = i; j < Gg * Dd; j += stride) { d_s1[j] = 0.f; d_q1[j] = 0.f; d_s2[j] = 0.f; d_q2[j] = 0.f; }
    for (int j = i; j < Gg; j += stride) d_cnt[j] = 0.f;
    for (int j = i; j < Nn; j += stride) d_deg[j] = 0;
}

// ---------------- per-graph moments (batch is SORTED int32: register-accumulate, flush on boundary)
// pass 0: input = x (param) -> d_s1/d_q1 (+counts). pass 1: input = d_y -> d_s2/d_q2.
__global__ void momentsKernel(const float* __restrict__ xin, const int* __restrict__ batch,
                              int pass) {
    const float* x = pass ? (const float*)d_y : xin;
    float* sum = pass ? d_s2 : d_s1;
    float* sq = pass ? d_q2 : d_q1;
    int doCnt = (pass == 0);
    int lane = threadIdx.x;                       // 0..31 -> dims lane*4..lane*4+3
    int r0 = blockIdx.x * 256 + threadIdx.y * 32; // this stream's first row
    float4 a = make_float4(0.f, 0.f, 0.f, 0.f);
    float4 q = make_float4(0.f, 0.f, 0.f, 0.f);
    float c = 0.f;
    int curg = -1;

#define FLUSH_MOM()                                                             \
    {                                                                           \
        int base = curg * Dd + lane * 4;                                        \
        atomicAdd(&sum[base + 0], a.x); atomicAdd(&sum[base + 1], a.y);         \
        atomicAdd(&sum[base + 2], a.z); atomicAdd(&sum[base + 3], a.w);         \
        atomicAdd(&sq[base + 0], q.x);  atomicAdd(&sq[base + 1], q.y);          \
        atomicAdd(&sq[base + 2], q.z);  atomicAdd(&sq[base + 3], q.w);          \
        if (doCnt && lane == 0) atomicAdd(&d_cnt[curg], c);                     \
    }

    for (int i = 0; i < 32; i++) {
        int r = r0 + i;
        if (r >= Nn) break;
        int g = __ldg(&batch[r]);
        if (g != curg) {
            if (curg >= 0) FLUSH_MOM();
            curg = g;
            a = make_float4(0.f, 0.f, 0.f, 0.f);
            q = make_float4(0.f, 0.f, 0.f, 0.f);
            c = 0.f;
        }
        float4 v = ((const float4*)x)[r * 32 + lane];
        a.x += v.x; a.y += v.y; a.z += v.z; a.w += v.w;
        q.x += v.x * v.x; q.y += v.y * v.y; q.z += v.z * v.z; q.w += v.w * v.w;
        c += 1.f;
    }
    if (curg >= 0) FLUSH_MOM();
#undef FLUSH_MOM
}

// ---------------- fold moments into affine (h = A*x + C) ----------------
// out = x - mean*ms ;  var = E[x^2] - (2ms - ms^2)*mean^2 ;  h = w*out*rstd + b = A*x + C
__global__ void statsKernel(const float* __restrict__ w, const float* __restrict__ b,
                            const float* __restrict__ ms, int pass) {
    const float* sum = pass ? d_s2 : d_s1;
    const float* sq = pass ? d_q2 : d_q1;
    float* A = pass ? d_A2 : d_A1;
    float* C = pass ? d_C2 : d_C1;
    int i = blockIdx.x * blockDim.x + threadIdx.x;
    if (i >= Gg * Dd) return;
    int g = i >> 7, dch = i & 127;
    float cnt = fmaxf(d_cnt[g], 1.f);
    float mean = sum[i] / cnt;
    float ex2 = sq[i] / cnt;
    float m = ms[dch];
    float var = ex2 - (2.f * m - m * m) * mean * mean;
    float rstd = rsqrtf(var + EPSV);
    float aa = w[dch] * rstd;
    A[i] = aa;
    C[i] = b[dch] - mean * m * aa;
}

// ---------------- apply affine per node ----------------
// pass 0: in = x (param), out = d_h, coeffs A1/C1.
// pass 1: in = d_y, out = dout (param), coeffs A2/C2.
__global__ void affineKernel(const float* __restrict__ xin, const int* __restrict__ batch,
                             float* __restrict__ dout, int pass) {
    const float* in = pass ? (const float*)d_y : xin;
    float* out = pass ? dout : (float*)d_h;
    const float* A = pass ? d_A2 : d_A1;
    const float* C = pass ? d_C2 : d_C1;
    int i = blockIdx.x * blockDim.x + threadIdx.x;  // float4 index
    if (i >= Nn * 32) return;
    int r = i >> 5, col = i & 31;
    int g = __ldg(&batch[r]);
    float4 v = ((const float4*)in)[i];
    float4 a = ((const float4*)A)[g * 32 + col];
    float4 c = ((const float4*)C)[g * 32 + col];
    float4 o;
    o.x = fmaf(a.x, v.x, c.x); o.y = fmaf(a.y, v.y, c.y);
    o.z = fmaf(a.z, v.z, c.z); o.w = fmaf(a.w, v.w, c.w);
    ((float4*)out)[i] = o;
}

// ---------------- CSR build: degree -> scan -> scatter ----------------
// edge_index is int32 [2, E]: src = ei[0..E), dst = ei[E..2E)
__global__ void degreeKernel(const int* __restrict__ ei) {
    int i = blockIdx.x * blockDim.x + threadIdx.x;
    if (i < Ee) atomicAdd(&d_deg[ei[Ee + i]], 1);
}

__global__ void scanBlocks() {  // 98 blocks x 1024 threads, exclusive scan within block
    __shared__ int wt[32];
    int i = blockIdx.x * 1024 + threadIdx.x;
    int v = (i < Nn) ? d_deg[i] : 0;
    int lane = threadIdx.x & 31, wd = threadIdx.x >> 5;
    int inc = v;
#pragma unroll
    for (int o = 1; o < 32; o <<= 1) {
        int t = __shfl_up_sync(0xffffffffu, inc, o);
        if (lane >= o) inc += t;
    }
    if (lane == 31) wt[wd] = inc;
    __syncthreads();
    if (wd == 0) {
        int t = wt[lane];
#pragma unroll
        for (int o = 1; o < 32; o <<= 1) {
            int u = __shfl_up_sync(0xffffffffu, t, o);
            if (lane >= o) t += u;
        }
        wt[lane] = t;
    }
    __syncthreads();
    int base = (wd > 0) ? wt[wd - 1] : 0;
    if (i < Nn) d_start[i] = base + inc - v;
    if (threadIdx.x == 1023) d_bsum[blockIdx.x] = base + inc;
}

__global__ void scanBsums() {  // 1 block, 128 threads; 98 valid entries -> exclusive
    __shared__ int s[128];
    int t = threadIdx.x;
    int v = (t < 98) ? d_bsum[t] : 0;
    s[t] = v;
    __syncthreads();
    for (int o = 1; o < 128; o <<= 1) {
        int u = (t >= o) ? s[t - o] : 0;
        __syncthreads();
        s[t] += u;
        __syncthreads();
    }
    if (t < 98) d_bsum[t] = s[t] - v;
}

__global__ void fixupKernel() {
    int i = blockIdx.x * blockDim.x + threadIdx.x;
    if (i < Nn) {
        int st = d_start[i] + d_bsum[i >> 10];
        d_start[i] = st;
        d_cur[i] = st;
    }
}

__global__ void scatterKernel(const int* __restrict__ ei) {
    int i = blockIdx.x * blockDim.x + threadIdx.x;
    if (i < Ee) {
        int dst = ei[Ee + i];
        int p = atomicAdd(&d_cur[dst], 1);
        d_srcs[p] = ei[i];
    }
}

// ---------------- segment-max aggregation: one warp per node, gather h[src] from L2 ----------------
__global__ void aggKernel() {
    int w = (blockIdx.x * blockDim.x + threadIdx.x) >> 5;
    int lane = threadIdx.x & 31;
    if (w >= Nn) return;
    int s = d_start[w], dg = d_deg[w];
    float4 acc = make_float4(-3.0e38f, -3.0e38f, -3.0e38f, -3.0e38f);
    for (int base = 0; base < dg; base += 32) {
        int rem = dg - base;
        if (rem > 32) rem = 32;
        int sc = (lane < rem) ? d_srcs[s + base + lane] : 0;
        for (int j = 0; j < rem; j++) {
            int scj = __shfl_sync(0xffffffffu, sc, j);
            float4 v = ((const float4*)d_h)[scj * 32 + lane];
            acc.x = fmaxf(acc.x, v.x); acc.y = fmaxf(acc.y, v.y);
            acc.z = fmaxf(acc.z, v.z); acc.w = fmaxf(acc.w, v.w);
        }
    }
    if (dg == 0) acc = make_float4(0.f, 0.f, 0.f, 0.f);  // PyG: empty segments -> 0
    ((float4*)d_agg)[w * 32 + lane] = acc;
}

// ---------------- fused GEMM: y = relu(x + agg@wl^T + b_l + h@wr^T) ----------------
// 128-node x 128-dim tile per block, 256 threads, STATIC smem (~34.6 KB, no opt-in).
// K = 256 (agg|h concat) in eight 32-wide chunks: chunks 0-3 use (d_agg, wl),
// chunks 4-7 use (d_h, wr). Thread (tm, tn): 8 rows x 4 dim-pairs, fma.rn.f32x2.
#define PA 36    // sA pitch (floats): mult of 4 -> 16B-aligned rows, conflict-free
#define PWc 130  // sW pitch (floats): even -> 8B-aligned ull rows
__global__ __launch_bounds__(256) void gemmKernel(const float* __restrict__ wl,
                                                  const float* __restrict__ wr,
                                                  const float* __restrict__ bl,
                                                  const float* __restrict__ x) {
    __shared__ __align__(16) float sA[128 * PA];   // sA[m][kk]
    __shared__ __align__(16) float sW[32 * PWc];   // sW[kk][n]
    int tid = threadIdx.x;
    int r0 = blockIdx.x * 128;
    int tm = tid >> 4, tn = tid & 15;

    ull acc[8][4];
#pragma unroll
    for (int i = 0; i < 8; i++)
#pragma unroll
        for (int j = 0; j < 4; j++) acc[i][j] = 0ull;

    const float* aBase = sA + tm * 8 * PA;

    for (int c = 0; c < 8; c++) {
        const float* src = (c < 4) ? (const float*)d_agg : (const float*)d_h;
        const float* W = (c < 4) ? wl : wr;
        int kbase = (c & 3) * 32;

        __syncthreads();  // previous chunk's compute done before refill
#pragma unroll
        for (int it = 0; it < 16; it++) {           // fill sA (coalesced, conflict-free)
            int idx = tid + it * 256;               // 0..4095
            int m = idx >> 5, kk = idx & 31;
            int r = r0 + m;
            sA[m * PA + kk] = (r < Nn) ? src[r * 128 + kbase + kk] : 0.f;
        }
#pragma unroll
        for (int it = 0; it < 16; it++) {           // fill sW transposed
            int idx = tid + it * 256;
            int n = idx >> 5, kk = idx & 31;
            sW[kk * PWc + n] = W[n * 128 + kbase + kk];
        }
        __syncthreads();

#pragma unroll
        for (int k = 0; k < 32; k += 4) {
            ull w[4][4];
#pragma unroll
            for (int kq = 0; kq < 4; kq++) {
                const ull* wp = (const ull*)(sW + (k + kq) * PWc) + tn;
                w[kq][0] = wp[0]; w[kq][1] = wp[16]; w[kq][2] = wp[32]; w[kq][3] = wp[48];
            }
#pragma unroll
            for (int mm = 0; mm < 8; mm++) {
                float4 a4 = *(const float4*)(aBase + mm * PA + k);
                ull a0 = pack2(a4.x), a1 = pack2(a4.y), a2 = pack2(a4.z), a3 = pack2(a4.w);
#pragma unroll
                for (int j = 0; j < 4; j++) {
                    FMA2(acc[mm][j], a0, w[0][j]);
                    FMA2(acc[mm][j], a1, w[1][j]);
                    FMA2(acc[mm][j], a2, w[2][j]);
                    FMA2(acc[mm][j], a3, w[3][j]);
                }
            }
        }
    }

#pragma unroll
    for (int mm = 0; mm < 8; mm++) {
        int r = r0 + tm * 8 + mm;
        if (r >= Nn) break;
#pragma unroll
        for (int j = 0; j < 4; j++) {
            int nn = tn * 2 + j * 32;
            float2 p = *(float2*)&acc[mm][j];
            float v0 = p.x + __ldg(&bl[nn]) + x[r * 128 + nn];
            float v1 = p.y + __ldg(&bl[nn + 1]) + x[r * 128 + nn + 1];
            d_y[r * 128 + nn] = fmaxf(v0, 0.f);
            d_y[r * 128 + nn + 1] = fmaxf(v1, 0.f);
        }
    }
}

// ---------------- launch (capture-safe: kernel launches ONLY) ----------------
extern "C" void kernel_launch(void* const* d_in, const int* in_sizes, int n_in,
                              void* d_out, int out_size) {
    const float* x = (const float*)d_in[0];
    const int* ei = (const int*)d_in[1];      // int32! (JAX x64 disabled downgrades int64)
    const int* batch = (const int*)d_in[2];   // int32!
    const float* n1w = (const float*)d_in[3];
    const float* n1b = (const float*)d_in[4];
    const float* n1ms = (const float*)d_in[5];
    const float* n2w = (const float*)d_in[6];
    const float* n2b = (const float*)d_in[7];
    const float* n2ms = (const float*)d_in[8];
    const float* wl = (const float*)d_in[9];
    const float* bl = (const float*)d_in[10];
    const float* wr = (const float*)d_in[11];
    float* out = (float*)d_out;

    zeroKernel<<<512, 256>>>();
    // ---- GraphNorm 1: x -> d_h ----
    momentsKernel<<<391, dim3(32, 8)>>>(x, batch, 0);
    statsKernel<<<128, 256>>>(n1w, n1b, n1ms, 0);
    affineKernel<<<12500, 256>>>(x, batch, out, 0);   // pass 0 writes d_h internally
    // ---- CSR build (by dst) ----
    degreeKernel<<<2344, 256>>>(ei);
    scanBlocks<<<98, 1024>>>();
    scanBsums<<<1, 128>>>();
    fixupKernel<<<391, 256>>>();
    scatterKernel<<<2344, 256>>>(ei);
    // ---- segment-max aggregation ----
    aggKernel<<<12500, 256>>>();
    // ---- fused SAGE GEMMs + bias + residual + relu -> d_y ----
    gemmKernel<<<782, 256>>>(wl, wr, bl, x);
    // ---- GraphNorm 2: d_y -> out ----
    momentsKernel<<<391, dim3(32, 8)>>>(x, batch, 1); // pass 1 reads d_y internally
    statsKernel<<<128, 256>>>(n2w, n2b, n2ms, 1);
    affineKernel<<<12500, 256>>>(x, batch, out, 1);   // pass 1 reads d_y, writes out
}

// round 9
// speedup vs baseline: 1.2507x; 1.2507x over previous
#include <cuda_runtime.h>
#include <cuda_bf16.h>

#define Nn 100000
#define Ee 600000
#define Dd 128
#define Gg 256
#define EPSV 1e-5f

typedef unsigned long long ull;
typedef unsigned int uint32;

// ---------------- scratch (device globals; no allocation allowed) ----------------
__device__ __align__(16) float d_h[Nn * Dd];     // normed features (GEMM input + gather source)
__device__ __align__(16) float d_agg[Nn * Dd];   // segment-max result
__device__ __align__(16) float d_y[Nn * Dd];     // relu(x + sage) pre-norm2
__device__ __align__(16) float d_s1[Gg * Dd], d_q1[Gg * Dd];
__device__ __align__(16) float d_s2[Gg * Dd], d_q2[Gg * Dd];
__device__ __align__(16) float d_A1[Gg * Dd], d_C1[Gg * Dd];
__device__ __align__(16) float d_A2[Gg * Dd], d_C2[Gg * Dd];
__device__ float d_cnt[Gg];
__device__ int d_deg[Nn], d_start[Nn], d_cur[Nn], d_srcs[Ee];
__device__ int d_bsum[128];

// ---------------- zero scratch ----------------
__global__ void zeroKernel() {
    int i = blockIdx.x * blockDim.x + threadIdx.x;
    int stride = gridDim.x * blockDim.x;
    for (int j = i; j < Gg * Dd; j += stride) { d_s1[j] = 0.f; d_q1[j] = 0.f; d_s2[j] = 0.f; d_q2[j] = 0.f; }
    for (int j = i; j < Gg; j += stride) d_cnt[j] = 0.f;
    for (int j = i; j < Nn; j += stride) d_deg[j] = 0;
}

// ---------------- per-graph moments (batch is SORTED int32: register-accumulate, flush on boundary)
__global__ void momentsKernel(const float* __restrict__ xin, const int* __restrict__ batch,
                              int pass) {
    const float* x = pass ? (const float*)d_y : xin;
    float* sum = pass ? d_s2 : d_s1;
    float* sq = pass ? d_q2 : d_q1;
    int doCnt = (pass == 0);
    int lane = threadIdx.x;                       // 0..31 -> dims lane*4..lane*4+3
    int r0 = blockIdx.x * 256 + threadIdx.y * 32; // this stream's first row
    float4 a = make_float4(0.f, 0.f, 0.f, 0.f);
    float4 q = make_float4(0.f, 0.f, 0.f, 0.f);
    float c = 0.f;
    int curg = -1;

#define FLUSH_MOM()                                                             \
    {                                                                           \
        int base = curg * Dd + lane * 4;                                        \
        atomicAdd(&sum[base + 0], a.x); atomicAdd(&sum[base + 1], a.y);         \
        atomicAdd(&sum[base + 2], a.z); atomicAdd(&sum[base + 3], a.w);         \
        atomicAdd(&sq[base + 0], q.x);  atomicAdd(&sq[base + 1], q.y);          \
        atomicAdd(&sq[base + 2], q.z);  atomicAdd(&sq[base + 3], q.w);          \
        if (doCnt && lane == 0) atomicAdd(&d_cnt[curg], c);                     \
    }

    for (int i = 0; i < 32; i++) {
        int r = r0 + i;
        if (r >= Nn) break;
        int g = __ldg(&batch[r]);
        if (g != curg) {
            if (curg >= 0) FLUSH_MOM();
            curg = g;
            a = make_float4(0.f, 0.f, 0.f, 0.f);
            q = make_float4(0.f, 0.f, 0.f, 0.f);
            c = 0.f;
        }
        float4 v = ((const float4*)x)[r * 32 + lane];
        a.x += v.x; a.y += v.y; a.z += v.z; a.w += v.w;
        q.x += v.x * v.x; q.y += v.y * v.y; q.z += v.z * v.z; q.w += v.w * v.w;
        c += 1.f;
    }
    if (curg >= 0) FLUSH_MOM();
#undef FLUSH_MOM
}

// ---------------- fold moments into affine (h = A*x + C) ----------------
__global__ void statsKernel(const float* __restrict__ w, const float* __restrict__ b,
                            const float* __restrict__ ms, int pass) {
    const float* sum = pass ? d_s2 : d_s1;
    const float* sq = pass ? d_q2 : d_q1;
    float* A = pass ? d_A2 : d_A1;
    float* C = pass ? d_C2 : d_C1;
    int i = blockIdx.x * blockDim.x + threadIdx.x;
    if (i >= Gg * Dd) return;
    int g = i >> 7, dch = i & 127;
    float cnt = fmaxf(d_cnt[g], 1.f);
    float mean = sum[i] / cnt;
    float ex2 = sq[i] / cnt;
    float m = ms[dch];
    float var = ex2 - (2.f * m - m * m) * mean * mean;
    float rstd = rsqrtf(var + EPSV);
    float aa = w[dch] * rstd;
    A[i] = aa;
    C[i] = b[dch] - mean * m * aa;
}

// ---------------- apply affine per node ----------------
__global__ void affineKernel(const float* __restrict__ xin, const int* __restrict__ batch,
                             float* __restrict__ dout, int pass) {
    const float* in = pass ? (const float*)d_y : xin;
    float* out = pass ? dout : (float*)d_h;
    const float* A = pass ? d_A2 : d_A1;
    const float* C = pass ? d_C2 : d_C1;
    int i = blockIdx.x * blockDim.x + threadIdx.x;  // float4 index
    if (i >= Nn * 32) return;
    int r = i >> 5, col = i & 31;
    int g = __ldg(&batch[r]);
    float4 v = ((const float4*)in)[i];
    float4 a = ((const float4*)A)[g * 32 + col];
    float4 c = ((const float4*)C)[g * 32 + col];
    float4 o;
    o.x = fmaf(a.x, v.x, c.x); o.y = fmaf(a.y, v.y, c.y);
    o.z = fmaf(a.z, v.z, c.z); o.w = fmaf(a.w, v.w, c.w);
    ((float4*)out)[i] = o;
}

// ---------------- CSR build: degree -> scan -> scatter ----------------
__global__ void degreeKernel(const int* __restrict__ ei) {
    int i = blockIdx.x * blockDim.x + threadIdx.x;
    if (i < Ee) atomicAdd(&d_deg[ei[Ee + i]], 1);
}

__global__ void scanBlocks() {  // 98 blocks x 1024 threads, exclusive scan within block
    __shared__ int wt[32];
    int i = blockIdx.x * 1024 + threadIdx.x;
    int v = (i < Nn) ? d_deg[i] : 0;
    int lane = threadIdx.x & 31, wd = threadIdx.x >> 5;
    int inc = v;
#pragma unroll
    for (int o = 1; o < 32; o <<= 1) {
        int t = __shfl_up_sync(0xffffffffu, inc, o);
        if (lane >= o) inc += t;
    }
    if (lane == 31) wt[wd] = inc;
    __syncthreads();
    if (wd == 0) {
        int t = wt[lane];
#pragma unroll
        for (int o = 1; o < 32; o <<= 1) {
            int u = __shfl_up_sync(0xffffffffu, t, o);
            if (lane >= o) t += u;
        }
        wt[lane] = t;
    }
    __syncthreads();
    int base = (wd > 0) ? wt[wd - 1] : 0;
    if (i < Nn) d_start[i] = base + inc - v;
    if (threadIdx.x == 1023) d_bsum[blockIdx.x] = base + inc;
}

__global__ void scanBsums() {  // 1 block, 128 threads; 98 valid entries -> exclusive
    __shared__ int s[128];
    int t = threadIdx.x;
    int v = (t < 98) ? d_bsum[t] : 0;
    s[t] = v;
    __syncthreads();
    for (int o = 1; o < 128; o <<= 1) {
        int u = (t >= o) ? s[t - o] : 0;
        __syncthreads();
        s[t] += u;
        __syncthreads();
    }
    if (t < 98) d_bsum[t] = s[t] - v;
}

__global__ void fixupKernel() {
    int i = blockIdx.x * blockDim.x + threadIdx.x;
    if (i < Nn) {
        int st = d_start[i] + d_bsum[i >> 10];
        d_start[i] = st;
        d_cur[i] = st;
    }
}

__global__ void scatterKernel(const int* __restrict__ ei) {
    int i = blockIdx.x * blockDim.x + threadIdx.x;
    if (i < Ee) {
        int dst = ei[Ee + i];
        int p = atomicAdd(&d_cur[dst], 1);
        d_srcs[p] = ei[i];
    }
}

// ---------------- segment-max aggregation: one warp per node ----------------
__global__ void aggKernel() {
    int w = (blockIdx.x * blockDim.x + threadIdx.x) >> 5;
    int lane = threadIdx.x & 31;
    if (w >= Nn) return;
    int s = d_start[w], dg = d_deg[w];
    float4 acc = make_float4(-3.0e38f, -3.0e38f, -3.0e38f, -3.0e38f);
    for (int base = 0; base < dg; base += 32) {
        int rem = dg - base;
        if (rem > 32) rem = 32;
        int sc = (lane < rem) ? d_srcs[s + base + lane] : 0;
        for (int j = 0; j < rem; j++) {
            int scj = __shfl_sync(0xffffffffu, sc, j);
            float4 v = ((const float4*)d_h)[scj * 32 + lane];
            acc.x = fmaxf(acc.x, v.x); acc.y = fmaxf(acc.y, v.y);
            acc.z = fmaxf(acc.z, v.z); acc.w = fmaxf(acc.w, v.w);
        }
    }
    if (dg == 0) acc = make_float4(0.f, 0.f, 0.f, 0.f);  // PyG: empty segments -> 0
    ((float4*)d_agg)[w * 32 + lane] = acc;
}

// ================= tensor-core GEMM (bf16 split, HMMA mma.sync) =================
// y = relu(x + agg@wl^T + b_l + h@wr^T), computed as ONE bf16 GEMM with K2 = 768:
//   segment 0 (k2   0..255): A = hi(agg|h),  W = hi(wl|wr)
//   segment 1 (k2 256..511): A = hi(agg|h),  W = lo(wl|wr)
//   segment 2 (k2 512..767): A = lo(agg|h),  W = hi(wl|wr)
// where hi(v) = bf16(v), lo(v) = bf16(v - float(bf16(v))). Dropped lo*lo ~ 2^-16.
// Block: 128 rows x 128 cols, 256 threads (8 warps, each m32 x n64).
// Fragments are PRE-PERMUTED in smem at fill time: one LDS.128 per A-frag,
// one LDS.64 per B-frag in the mainloop. 12 chunks of k2=64 (32 KB static smem).

__device__ __forceinline__ uint32 packbf(float lo, float hi) {
    uint32 r;
    asm("cvt.rn.bf16x2.f32 %0, %1, %2;" : "=r"(r) : "f"(hi), "f"(lo));
    return r;
}

__device__ __forceinline__ void mma16816(float* c, const uint32* a, const uint32* b) {
    asm volatile(
        "mma.sync.aligned.m16n8k16.row.col.f32.bf16.bf16.f32 "
        "{%0,%1,%2,%3}, {%4,%5,%6,%7}, {%8,%9}, {%0,%1,%2,%3};"
        : "+f"(c[0]), "+f"(c[1]), "+f"(c[2]), "+f"(c[3])
        : "r"(a[0]), "r"(a[1]), "r"(a[2]), "r"(a[3]), "r"(b[0]), "r"(b[1]));
}

__global__ __launch_bounds__(256) void gemmKernel(const float* __restrict__ wl,
                                                  const float* __restrict__ wr,
                                                  const float* __restrict__ bl,
                                                  const float* __restrict__ x) {
    // aS: [m16 0..7][kstep 0..3][lane 0..31][4 u32]  -> 4096 u32 = 16 KB
    // bS: [kstep 0..3][n8 0..15][lane 0..31][2 u32]  -> 4096 u32 = 16 KB
    __shared__ __align__(16) uint32 aS[4096];
    __shared__ __align__(16) uint32 bS[4096];

    int tid = threadIdx.x;
    int lane = tid & 31, wid = tid >> 5;
    int warpM = wid >> 1, warpN = wid & 1;
    int r0 = blockIdx.x * 128;

    float acc[2][8][4];
#pragma unroll
    for (int mi = 0; mi < 2; mi++)
#pragma unroll
        for (int j = 0; j < 8; j++)
#pragma unroll
            for (int q = 0; q < 4; q++) acc[mi][j][q] = 0.f;

    for (int c = 0; c < 12; c++) {
        int seg = c >> 2;            // 0,1,2
        int ks0 = (c & 3) * 64;      // 0,64,128,192 within K=256
        int aLo = (seg == 2);
        int wLo = (seg == 1);
        const float* srcA = (ks0 < 128) ? (const float*)d_agg : (const float*)d_h;
        const float* srcW = (ks0 < 128) ? wl : wr;
        int koff = ks0 & 127;

        __syncthreads();  // previous chunk's compute done before refill

        // ---- fill A fragments (coalesced float2 gmem reads) ----
#pragma unroll
        for (int it = 0; it < 16; it++) {
            int idx = tid + it * 256;           // 0..4095 (row, k-pair)
            int row = idx >> 5, kp = idx & 31;
            int r = r0 + row;
            float2 v = make_float2(0.f, 0.f);
            if (r < Nn) v = *(const float2*)(srcA + r * 128 + koff + kp * 2);
            float h0 = __bfloat162float(__float2bfloat16(v.x));
            float h1 = __bfloat162float(__float2bfloat16(v.y));
            uint32 pk = aLo ? packbf(v.x - h0, v.y - h1) : packbf(v.x, v.y);
            int m16 = row >> 4, rr = row & 15;
            int kstep = kp >> 3, p = kp & 7;
            int t = (rr & 7) * 4 + (p & 3);
            int reg = (rr >> 3) + ((p >> 2) << 1);
            aS[((m16 * 4 + kstep) * 32 + t) * 4 + reg] = pk;
        }
        // ---- fill B fragments ----
#pragma unroll
        for (int it = 0; it < 16; it++) {
            int idx = tid + it * 256;           // (n, k-pair)
            int n = idx >> 5, kp = idx & 31;
            float2 v = *(const float2*)(srcW + n * 128 + koff + kp * 2);
            float h0 = __bfloat162float(__float2bfloat16(v.x));
            float h1 = __bfloat162float(__float2bfloat16(v.y));
            uint32 pk = wLo ? packbf(v.x - h0, v.y - h1) : packbf(v.x, v.y);
            int kstep = kp >> 3, p = kp & 7;
            int n8 = n >> 3, nn = n & 7;
            int t = nn * 4 + (p & 3);
            int reg = p >> 2;
            bS[((kstep * 16 + n8) * 32 + t) * 2 + reg] = pk;
        }
        __syncthreads();

        // ---- mainloop: 4 ksteps x 16 HMMA per warp ----
#pragma unroll
        for (int kstep = 0; kstep < 4; kstep++) {
            uint32 a[2][4];
#pragma unroll
            for (int mi = 0; mi < 2; mi++) {
                int m16 = warpM * 2 + mi;
                *(uint4*)a[mi] = *(const uint4*)&aS[((m16 * 4 + kstep) * 32 + lane) * 4];
            }
#pragma unroll
            for (int j = 0; j < 8; j++) {
                uint32 b[2];
                *(uint2*)b = *(const uint2*)&bS[((kstep * 16 + warpN * 8 + j) * 32 + lane) * 2];
                mma16816(acc[0][j], a[0], b);
                mma16816(acc[1][j], a[1], b);
            }
        }
    }

    // ---- epilogue: bias + residual + relu -> d_y ----
#pragma unroll
    for (int mi = 0; mi < 2; mi++) {
        int rbase = r0 + warpM * 32 + mi * 16 + (lane >> 2);
#pragma unroll
        for (int j = 0; j < 8; j++) {
            int nc = warpN * 64 + j * 8 + (lane & 3) * 2;
            float b0 = __ldg(&bl[nc]), b1 = __ldg(&bl[nc + 1]);
            int r = rbase;
            if (r < Nn) {
                float2 xv = *(const float2*)(x + r * 128 + nc);
                float2 o;
                o.x = fmaxf(acc[mi][j][0] + b0 + xv.x, 0.f);
                o.y = fmaxf(acc[mi][j][1] + b1 + xv.y, 0.f);
                *(float2*)(d_y + r * 128 + nc) = o;
            }
            r = rbase + 8;
            if (r < Nn) {
                float2 xv = *(const float2*)(x + r * 128 + nc);
                float2 o;
                o.x = fmaxf(acc[mi][j][2] + b0 + xv.x, 0.f);
                o.y = fmaxf(acc[mi][j][3] + b1 + xv.y, 0.f);
                *(float2*)(d_y + r * 128 + nc) = o;
            }
        }
    }
}

// ---------------- launch (capture-safe: kernel launches ONLY) ----------------
extern "C" void kernel_launch(void* const* d_in, const int* in_sizes, int n_in,
                              void* d_out, int out_size) {
    const float* x = (const float*)d_in[0];
    const int* ei = (const int*)d_in[1];      // int32 (JAX x64 disabled)
    const int* batch = (const int*)d_in[2];   // int32
    const float* n1w = (const float*)d_in[3];
    const float* n1b = (const float*)d_in[4];
    const float* n1ms = (const float*)d_in[5];
    const float* n2w = (const float*)d_in[6];
    const float* n2b = (const float*)d_in[7];
    const float* n2ms = (const float*)d_in[8];
    const float* wl = (const float*)d_in[9];
    const float* bl = (const float*)d_in[10];
    const float* wr = (const float*)d_in[11];
    float* out = (float*)d_out;

    zeroKernel<<<512, 256>>>();
    // ---- GraphNorm 1: x -> d_h ----
    momentsKernel<<<391, dim3(32, 8)>>>(x, batch, 0);
    statsKernel<<<128, 256>>>(n1w, n1b, n1ms, 0);
    affineKernel<<<12500, 256>>>(x, batch, out, 0);   // pass 0 writes d_h internally
    // ---- CSR build (by dst) ----
    degreeKernel<<<2344, 256>>>(ei);
    scanBlocks<<<98, 1024>>>();
    scanBsums<<<1, 128>>>();
    fixupKernel<<<391, 256>>>();
    scatterKernel<<<2344, 256>>>(ei);
    // ---- segment-max aggregation ----
    aggKernel<<<12500, 256>>>();
    // ---- fused SAGE GEMMs + bias + residual + relu -> d_y (tensor cores) ----
    gemmKernel<<<782, 256>>>(wl, wr, bl, x);
    // ---- GraphNorm 2: d_y -> out ----
    momentsKernel<<<391, dim3(32, 8)>>>(x, batch, 1); // pass 1 reads d_y internally
    statsKernel<<<128, 256>>>(n2w, n2b, n2ms, 1);
    affineKernel<<<12500, 256>>>(x, batch, out, 1);   // pass 1 reads d_y, writes out
}